// round 15
// baseline (speedup 1.0000x reference)
#include <cuda_runtime.h>
#include <cuda_fp16.h>
#include <cuda_bf16.h>
#include <cstdint>

// LSTM B=2048,T=512,F=64,H=128.
// Prepass: xz = x@Wx + b as a batched GEMM (single-term fp16 mma), M=128
//   (16 rows x 8 timesteps), N=512, K=64; fp16 quads to g_xzh in rec layout.
// Rec (R15): R13 config (256 thr / 8 warps, warp owns 64 gate cols), but
//   SINGLE sync per step: epilogue writes h directly to gmem out (scattered
//   STG.32, L2 merges) and directly into the A(t+1) half buffer (STS.16).
//   No stage, no second barrier.

#define T_DIM 512
#define F_DIM 64
#define H_DIM 128
#define TFX   (T_DIM * F_DIM)
#define THX   (T_DIM * H_DIM)
#define NTH   256

// rec smem
#define R_W   0
#define R_A   131072            // 2 x 4096 (A fp16 [16][128], double buffer)
#define SMEM_REC (R_A + 8192)

// prepass smem
#define P_W   0                 // W fp16 [512][64] ldmatrix layout, 64KB
#define P_A   65536             // A fp16 [128][64], double buffer 2x16KB
#define SMEM_PRE 98304

typedef uint32_t u32;
typedef unsigned long long u64;

__device__ uint2 g_xzh[134217728];   // 128 x 512 x 8 x 256 uint2 (1.07 GB)

static __device__ __forceinline__ u32 smaddr(const void* p) {
    u32 a;
    asm("{ .reg .u64 t; cvta.to.shared.u64 t, %1; cvt.u32.u64 %0, t; }" : "=r"(a) : "l"(p));
    return a;
}
static __device__ __forceinline__ void ldm4(u32* r, u32 ad) {
    asm volatile("ldmatrix.sync.aligned.m8n8.x4.shared.b16 {%0,%1,%2,%3}, [%4];"
                 : "=r"(r[0]), "=r"(r[1]), "=r"(r[2]), "=r"(r[3]) : "r"(ad));
}
static __device__ __forceinline__ void ldm2(u32& a, u32& b, u32 ad) {
    asm volatile("ldmatrix.sync.aligned.m8n8.x2.shared.b16 {%0,%1}, [%2];"
                 : "=r"(a), "=r"(b) : "r"(ad));
}
static __device__ __forceinline__ void mma_f16(float* c, const u32* a, u32 b0, u32 b1) {
    asm volatile(
        "mma.sync.aligned.m16n8k16.row.col.f32.f16.f16.f32 "
        "{%0,%1,%2,%3}, {%4,%5,%6,%7}, {%8,%9}, {%0,%1,%2,%3};"
        : "+f"(c[0]), "+f"(c[1]), "+f"(c[2]), "+f"(c[3])
        : "r"(a[0]), "r"(a[1]), "r"(a[2]), "r"(a[3]), "r"(b0), "r"(b1));
}
static __device__ __forceinline__ float tanh_ap(float x) {
    float r; asm("tanh.approx.f32 %0, %1;" : "=f"(r) : "f"(x)); return r;
}
static __device__ __forceinline__ float sig_ap(float x) {
    return fmaf(0.5f, tanh_ap(0.5f * x), 0.5f);
}
static __device__ __forceinline__ u32 cath(float a, float b) {
    __half2 h2 = __floats2half2_rn(a, b);
    return *(u32*)&h2;
}

// ============================ prepass ======================================
__global__ __launch_bounds__(NTH)
void lstm_prepass(const float* __restrict__ x, const float* __restrict__ Wx,
                  const float* __restrict__ bias)
{
    extern __shared__ char smc[];
    const u32 sb = smaddr(smc);
    const int tid = threadIdx.x, w = tid >> 5, lane = tid & 31;
    const int cta = blockIdx.x >> 2;
    const int t0 = (blockIdx.x & 3) * 128;
    const long b0 = (long)cta * 16;

    // W fp16, ldmatrix layout [n=512][k=64], 128B rows
    for (int idx = tid; idx < 512 * 64; idx += NTH) {
        int n = idx >> 6, k = idx & 63;
        int col = 128 * (n & 3) + (n >> 2);
        __half hv = __float2half_rn(Wx[k * 512 + col]);
        u32 off = (u32)(n * 128 + (((k >> 3) ^ (n & 7)) << 4) + (k & 7) * 2);
        *(__half*)(smc + P_W + off) = hv;
    }
    __syncthreads();

    const int amat = lane >> 3, aidx = lane & 7;
    const int arow = ((amat & 1) << 3) + aidx;
    const int aksel = amat >> 1;
    const int a7 = arow & 7;
    const int bl_ = lane & 15, brin = bl_ & 7, bksel = bl_ >> 3;

    u32 Br[4][8][2];
#pragma unroll
    for (int ks = 0; ks < 4; ks++) {
        const u32 swB = 16u * (u32)((2 * ks + bksel) ^ brin);
#pragma unroll
        for (int nj = 0; nj < 8; nj++)
            ldm2(Br[ks][nj][0], Br[ks][nj][1],
                 sb + P_W + (u32)((64 * w + 8 * nj + brin) * 128) + swB);
    }

    const int t4 = lane & 3;
    float b2[8][2];
#pragma unroll
    for (int nj = 0; nj < 8; nj++)
#pragma unroll
        for (int e = 0; e < 2; e++) {
            int n = 64 * w + 8 * nj + 2 * t4 + e;
            b2[nj][e] = bias[128 * (n & 3) + (n >> 2)];
        }

    const int brow = tid >> 1, part = tid & 1;
    const int tt = brow >> 4, bb = brow & 15;
    const float* xbase = x + (b0 + bb) * (long)TFX + (t0 + tt) * F_DIM + 32 * part;
    u32 aoff[4];
#pragma unroll
    for (int j = 0; j < 4; j++)
        aoff[j] = (u32)(brow * 128 + (((4 * part + j) ^ (brow & 7)) << 4));

    auto build = [&](int it, int buf) {
        const float* s = xbase + it * 8 * F_DIM;
        float4 q[8];
#pragma unroll
        for (int j = 0; j < 8; j++) q[j] = *(const float4*)(s + 4 * j);
        const u32 base = (u32)(P_A + buf * 16384);
#pragma unroll
        for (int j = 0; j < 4; j++) {
            uint4 pk;
            pk.x = cath(q[2 * j].x, q[2 * j].y);
            pk.y = cath(q[2 * j].z, q[2 * j].w);
            pk.z = cath(q[2 * j + 1].x, q[2 * j + 1].y);
            pk.w = cath(q[2 * j + 1].z, q[2 * j + 1].w);
            *(uint4*)(smc + base + aoff[j]) = pk;
        }
    };

    build(0, 0);
    __syncthreads();

    for (int it = 0; it < 16; it++) {
        if (it + 1 < 16) build(it + 1, (it + 1) & 1);

        const u32 ab = sb + P_A + (u32)((it & 1) * 16384);
#pragma unroll
        for (int mi = 0; mi < 8; mi++) {
            float acc[8][4];
#pragma unroll
            for (int nj = 0; nj < 8; nj++)
#pragma unroll
                for (int e = 0; e < 4; e++) acc[nj][e] = 0.0f;

#pragma unroll
            for (int ks = 0; ks < 4; ks++) {
                u32 A0[4];
                ldm4(A0, ab + (u32)((16 * mi + arow) * 128)
                         + 16u * (u32)((2 * ks + aksel) ^ a7));
#pragma unroll
                for (int nj = 0; nj < 8; nj++)
                    mma_f16(acc[nj], A0, Br[ks][nj][0], Br[ks][nj][1]);
            }

            const int t = t0 + 8 * it + mi;
            uint2* dst = g_xzh + ((long)cta * T_DIM + t) * 2048 + tid;
#pragma unroll
            for (int nj = 0; nj < 8; nj++) {
                uint2 pk;
                pk.x = cath(acc[nj][0] + b2[nj][0], acc[nj][1] + b2[nj][1]);
                pk.y = cath(acc[nj][2] + b2[nj][0], acc[nj][3] + b2[nj][1]);
                dst[nj * 256] = pk;
            }
        }
        __syncthreads();
    }
}

// ============================ recurrent ====================================
// 256 threads / 8 warps; warp w owns gate cols [64w, 64w+64) = 8 n-tiles.
// Single barrier per step; epilogue writes out + A(t+1) directly.
__global__ __launch_bounds__(NTH)
void lstm_rec(const float* __restrict__ Wh, float* __restrict__ out)
{
    extern __shared__ char smc[];
    const u32 sb = smaddr(smc);
    const int tid = threadIdx.x, w = tid >> 5, lane = tid & 31;
    const int cta = blockIdx.x;
    const long b0 = (long)cta * 16;

    // Wh fp16 [n=512][k=128], ldmatrix layout, 256B rows
    for (int idx = tid; idx < 512 * 128; idx += NTH) {
        int n = idx >> 7, k = idx & 127;
        int col = 128 * (n & 3) + (n >> 2);
        __half hv = __float2half_rn(Wh[k * 512 + col]);
        u32 off = (u32)(n * 256 + (((k >> 3) ^ (n & 7)) << 4) + (k & 7) * 2);
        *(__half*)(smc + R_W + off) = hv;
    }
    for (int i = tid; i < 8192 / 8; i += NTH)
        ((u64*)(smc + R_A))[i] = 0ull;
    __syncthreads();

    // fragment decode
    const int amat = lane >> 3, aidx = lane & 7;
    const int arow = ((amat & 1) << 3) + aidx;
    const int aksel = amat >> 1;
    const int a7 = arow & 7;
    const int bl_ = lane & 15, brin = bl_ & 7, bksel = bl_ >> 3;
    u32 bob[8];
#pragma unroll
    for (int nj = 0; nj < 8; nj++)
        bob[nj] = sb + R_W + (u32)((64 * w + 8 * nj + brin) * 256);

    // hoist B fragments for nj 0..3 (held for all 512 steps)
    u32 Br[8][4][2];
#pragma unroll
    for (int ks = 0; ks < 8; ks++) {
        const u32 swB = 16u * (u32)((2 * ks + bksel) ^ brin);
#pragma unroll
        for (int nj = 0; nj < 4; nj++)
            ldm2(Br[ks][nj][0], Br[ks][nj][1], bob[nj] + swB);
    }

    // epilogue decode: thread owns h(erow, col j = 16w + 2nj + hcsel), nj 0..7
    const int q = lane >> 2, t4 = lane & 3, rs = t4 & 1, hcsel = t4 >> 1;
    const int erow = q + 8 * rs;

    // direct-write addressing
    float* obase = out + (b0 + erow) * (long)THX + 16 * w + hcsel;
    u32 aoffs[8];
#pragma unroll
    for (int nj = 0; nj < 8; nj++) {
        int j = 16 * w + 2 * nj + hcsel;
        aoffs[nj] = (u32)(erow * 256 + (((j >> 3) ^ (erow & 7)) << 4) + ((j & 7) * 2));
    }

    const uint2* xzp = g_xzh + (long)cta * T_DIM * 2048;
    uint2 xz[8];
#pragma unroll
    for (int nj = 0; nj < 8; nj++)
        xz[nj] = xzp[nj * 256 + tid];

    float cst[8];
#pragma unroll
    for (int nj = 0; nj < 8; nj++) cst[nj] = 0.0f;

    for (int t = 0; t < T_DIM; t++) {
        __syncthreads();   // A(t) complete (incl. all STS-h from prev step)

        const u32 aob = sb + R_A + (u32)((t & 1) * 4096) + (u32)(arow * 256);

        float acc[8][4];
#pragma unroll
        for (int nj = 0; nj < 8; nj++)
#pragma unroll
            for (int e = 0; e < 4; e++) acc[nj][e] = 0.0f;

#pragma unroll
        for (int ks = 0; ks < 8; ks++) {
            u32 A0[4];
            ldm4(A0, aob + 16u * (u32)((2 * ks + aksel) ^ a7));
            const u32 swB = 16u * (u32)((2 * ks + bksel) ^ brin);
            u32 B4[4][2];
#pragma unroll
            for (int nj = 4; nj < 8; nj++)
                ldm2(B4[nj - 4][0], B4[nj - 4][1], bob[nj] + swB);
#pragma unroll
            for (int nj = 0; nj < 4; nj++)
                mma_f16(acc[nj], A0, Br[ks][nj][0], Br[ks][nj][1]);
#pragma unroll
            for (int nj = 4; nj < 8; nj++)
                mma_f16(acc[nj], A0, B4[nj - 4][0], B4[nj - 4][1]);
        }

        // epilogue: gates + state update; write h straight to out and A(t+1)
        float h8[8];
#pragma unroll
        for (int nj = 0; nj < 8; nj++) {
            float2 xlo = __half22float2(*(__half2*)&xz[nj].x);
            float2 xhi = __half22float2(*(__half2*)&xz[nj].y);
            float v0 = acc[nj][0] + xlo.x;
            float v1 = acc[nj][1] + xlo.y;
            float v2 = acc[nj][2] + xhi.x;
            float v3 = acc[nj][3] + xhi.y;
            float p0 = __shfl_xor_sync(0xffffffffu, v0, 1);
            float p1 = __shfl_xor_sync(0xffffffffu, v1, 1);
            float p2 = __shfl_xor_sync(0xffffffffu, v2, 1);
            float p3 = __shfl_xor_sync(0xffffffffu, v3, 1);
            float zi = rs ? p2 : v0;
            float zf = rs ? p3 : v1;
            float zg = rs ? v2 : p0;
            float zo = rs ? v3 : p1;
            float ig = sig_ap(zi);
            float fg = sig_ap(zf);
            float gg = tanh_ap(zg);
            float og = sig_ap(zo);
            float cn = fmaf(fg, cst[nj], ig * gg);
            cst[nj] = cn;
            float h = og * tanh_ap(cn);
            h8[nj] = h;
            obase[(long)t * H_DIM + 2 * nj] = h;          // scattered STG.32
        }
        if (t + 1 < T_DIM) {
            const u32 anext = sb + R_A + (u32)(((t + 1) & 1) * 4096);
#pragma unroll
            for (int nj = 0; nj < 8; nj++)
                *(__half*)((char*)smc + (anext - sb) + aoffs[nj]) =
                    __float2half_rn(h8[nj]);              // STS.16 into A(t+1)
        }

        // prefetch xz(t+1) (after LDSM/MMA phase)
        if (t + 1 < T_DIM) {
            const uint2* s = xzp + (long)(t + 1) * 2048 + tid;
#pragma unroll
            for (int nj = 0; nj < 8; nj++)
                xz[nj] = s[nj * 256];
        }
    }
}

extern "C" void kernel_launch(void* const* d_in, const int* in_sizes, int n_in,
                              void* d_out, int out_size) {
    const float* x  = (const float*)d_in[0];   // [B,T,F]
    const float* Wx = (const float*)d_in[1];   // [F,512]
    const float* Wh = (const float*)d_in[2];   // [H,512]
    const float* b  = (const float*)d_in[3];   // [512]
    float* out = (float*)d_out;                // [B,T,H]

    cudaFuncSetAttribute(lstm_prepass, cudaFuncAttributeMaxDynamicSharedMemorySize, SMEM_PRE);
    cudaFuncSetAttribute(lstm_rec, cudaFuncAttributeMaxDynamicSharedMemorySize, SMEM_REC);

    lstm_prepass<<<512, NTH, SMEM_PRE>>>(x, Wx, b);
    lstm_rec<<<128, NTH, SMEM_REC>>>(Wh, out);
}

// round 16
// speedup vs baseline: 1.6330x; 1.6330x over previous
#include <cuda_runtime.h>
#include <cuda_fp16.h>
#include <cuda_bf16.h>
#include <cstdint>

// LSTM B=2048,T=512,F=64,H=128.
// Prepass: xz = x@Wx + b as a batched GEMM (single-term fp16 mma), M=128
//   (16 rows x 8 timesteps), N=512, K=64; fp16 quads to g_xzh in rec layout.
// Rec (R16): 256 thr / 8 warps, warp owns 64 gate cols. SINGLE sync/step:
//   epilogue writes h directly into A(t+1) (STS.16) and into a parity-double-
//   buffered fp32 stage; the coalesced STG.128 of step t-1's h happens during
//   step t's MMA phase (overlapped). Final step's out-write peeled post-loop.

#define T_DIM 512
#define F_DIM 64
#define H_DIM 128
#define TFX   (T_DIM * F_DIM)
#define THX   (T_DIM * H_DIM)
#define NTH   256

// rec smem
#define R_W   0
#define R_A   131072            // 2 x 4096 (A fp16 [16][128], double buffer)
#define R_ST  139264            // stage fp32 2 x [16][132] (parity buffers)
#define STG_B 8448              // bytes per stage buffer
#define SMEM_REC (R_ST + 2 * STG_B)

// prepass smem
#define P_W   0                 // W fp16 [512][64] ldmatrix layout, 64KB
#define P_A   65536             // A fp16 [128][64], double buffer 2x16KB
#define SMEM_PRE 98304

typedef uint32_t u32;
typedef unsigned long long u64;

__device__ uint2 g_xzh[134217728];   // 128 x 512 x 8 x 256 uint2 (1.07 GB)

static __device__ __forceinline__ u32 smaddr(const void* p) {
    u32 a;
    asm("{ .reg .u64 t; cvta.to.shared.u64 t, %1; cvt.u32.u64 %0, t; }" : "=r"(a) : "l"(p));
    return a;
}
static __device__ __forceinline__ void ldm4(u32* r, u32 ad) {
    asm volatile("ldmatrix.sync.aligned.m8n8.x4.shared.b16 {%0,%1,%2,%3}, [%4];"
                 : "=r"(r[0]), "=r"(r[1]), "=r"(r[2]), "=r"(r[3]) : "r"(ad));
}
static __device__ __forceinline__ void ldm2(u32& a, u32& b, u32 ad) {
    asm volatile("ldmatrix.sync.aligned.m8n8.x2.shared.b16 {%0,%1}, [%2];"
                 : "=r"(a), "=r"(b) : "r"(ad));
}
static __device__ __forceinline__ void mma_f16(float* c, const u32* a, u32 b0, u32 b1) {
    asm volatile(
        "mma.sync.aligned.m16n8k16.row.col.f32.f16.f16.f32 "
        "{%0,%1,%2,%3}, {%4,%5,%6,%7}, {%8,%9}, {%0,%1,%2,%3};"
        : "+f"(c[0]), "+f"(c[1]), "+f"(c[2]), "+f"(c[3])
        : "r"(a[0]), "r"(a[1]), "r"(a[2]), "r"(a[3]), "r"(b0), "r"(b1));
}
static __device__ __forceinline__ float tanh_ap(float x) {
    float r; asm("tanh.approx.f32 %0, %1;" : "=f"(r) : "f"(x)); return r;
}
static __device__ __forceinline__ float sig_ap(float x) {
    return fmaf(0.5f, tanh_ap(0.5f * x), 0.5f);
}
static __device__ __forceinline__ u32 cath(float a, float b) {
    __half2 h2 = __floats2half2_rn(a, b);
    return *(u32*)&h2;
}

// ============================ prepass ======================================
__global__ __launch_bounds__(NTH)
void lstm_prepass(const float* __restrict__ x, const float* __restrict__ Wx,
                  const float* __restrict__ bias)
{
    extern __shared__ char smc[];
    const u32 sb = smaddr(smc);
    const int tid = threadIdx.x, w = tid >> 5, lane = tid & 31;
    const int cta = blockIdx.x >> 2;
    const int t0 = (blockIdx.x & 3) * 128;
    const long b0 = (long)cta * 16;

    // W fp16, ldmatrix layout [n=512][k=64], 128B rows
    for (int idx = tid; idx < 512 * 64; idx += NTH) {
        int n = idx >> 6, k = idx & 63;
        int col = 128 * (n & 3) + (n >> 2);
        __half hv = __float2half_rn(Wx[k * 512 + col]);
        u32 off = (u32)(n * 128 + (((k >> 3) ^ (n & 7)) << 4) + (k & 7) * 2);
        *(__half*)(smc + P_W + off) = hv;
    }
    __syncthreads();

    const int amat = lane >> 3, aidx = lane & 7;
    const int arow = ((amat & 1) << 3) + aidx;
    const int aksel = amat >> 1;
    const int a7 = arow & 7;
    const int bl_ = lane & 15, brin = bl_ & 7, bksel = bl_ >> 3;

    u32 Br[4][8][2];
#pragma unroll
    for (int ks = 0; ks < 4; ks++) {
        const u32 swB = 16u * (u32)((2 * ks + bksel) ^ brin);
#pragma unroll
        for (int nj = 0; nj < 8; nj++)
            ldm2(Br[ks][nj][0], Br[ks][nj][1],
                 sb + P_W + (u32)((64 * w + 8 * nj + brin) * 128) + swB);
    }

    const int t4 = lane & 3;
    float b2[8][2];
#pragma unroll
    for (int nj = 0; nj < 8; nj++)
#pragma unroll
        for (int e = 0; e < 2; e++) {
            int n = 64 * w + 8 * nj + 2 * t4 + e;
            b2[nj][e] = bias[128 * (n & 3) + (n >> 2)];
        }

    const int brow = tid >> 1, part = tid & 1;
    const int tt = brow >> 4, bb = brow & 15;
    const float* xbase = x + (b0 + bb) * (long)TFX + (t0 + tt) * F_DIM + 32 * part;
    u32 aoff[4];
#pragma unroll
    for (int j = 0; j < 4; j++)
        aoff[j] = (u32)(brow * 128 + (((4 * part + j) ^ (brow & 7)) << 4));

    auto build = [&](int it, int buf) {
        const float* s = xbase + it * 8 * F_DIM;
        float4 q[8];
#pragma unroll
        for (int j = 0; j < 8; j++) q[j] = *(const float4*)(s + 4 * j);
        const u32 base = (u32)(P_A + buf * 16384);
#pragma unroll
        for (int j = 0; j < 4; j++) {
            uint4 pk;
            pk.x = cath(q[2 * j].x, q[2 * j].y);
            pk.y = cath(q[2 * j].z, q[2 * j].w);
            pk.z = cath(q[2 * j + 1].x, q[2 * j + 1].y);
            pk.w = cath(q[2 * j + 1].z, q[2 * j + 1].w);
            *(uint4*)(smc + base + aoff[j]) = pk;
        }
    };

    build(0, 0);
    __syncthreads();

    for (int it = 0; it < 16; it++) {
        if (it + 1 < 16) build(it + 1, (it + 1) & 1);

        const u32 ab = sb + P_A + (u32)((it & 1) * 16384);
#pragma unroll
        for (int mi = 0; mi < 8; mi++) {
            float acc[8][4];
#pragma unroll
            for (int nj = 0; nj < 8; nj++)
#pragma unroll
                for (int e = 0; e < 4; e++) acc[nj][e] = 0.0f;

#pragma unroll
            for (int ks = 0; ks < 4; ks++) {
                u32 A0[4];
                ldm4(A0, ab + (u32)((16 * mi + arow) * 128)
                         + 16u * (u32)((2 * ks + aksel) ^ a7));
#pragma unroll
                for (int nj = 0; nj < 8; nj++)
                    mma_f16(acc[nj], A0, Br[ks][nj][0], Br[ks][nj][1]);
            }

            const int t = t0 + 8 * it + mi;
            uint2* dst = g_xzh + ((long)cta * T_DIM + t) * 2048 + tid;
#pragma unroll
            for (int nj = 0; nj < 8; nj++) {
                uint2 pk;
                pk.x = cath(acc[nj][0] + b2[nj][0], acc[nj][1] + b2[nj][1]);
                pk.y = cath(acc[nj][2] + b2[nj][0], acc[nj][3] + b2[nj][1]);
                dst[nj * 256] = pk;
            }
        }
        __syncthreads();
    }
}

// ============================ recurrent ====================================
// 256 threads / 8 warps; warp w owns gate cols [64w, 64w+64) = 8 n-tiles.
// Single barrier per step. Out-STG of step t-1 overlapped with MMA(t).
__global__ __launch_bounds__(NTH)
void lstm_rec(const float* __restrict__ Wh, float* __restrict__ out)
{
    extern __shared__ char smc[];
    const u32 sb = smaddr(smc);
    const int tid = threadIdx.x, w = tid >> 5, lane = tid & 31;
    const int cta = blockIdx.x;
    const long b0 = (long)cta * 16;

    // Wh fp16 [n=512][k=128], ldmatrix layout, 256B rows
    for (int idx = tid; idx < 512 * 128; idx += NTH) {
        int n = idx >> 7, k = idx & 127;
        int col = 128 * (n & 3) + (n >> 2);
        __half hv = __float2half_rn(Wh[k * 512 + col]);
        u32 off = (u32)(n * 256 + (((k >> 3) ^ (n & 7)) << 4) + (k & 7) * 2);
        *(__half*)(smc + R_W + off) = hv;
    }
    for (int i = tid; i < 8192 / 8; i += NTH)
        ((u64*)(smc + R_A))[i] = 0ull;
    __syncthreads();

    // fragment decode
    const int amat = lane >> 3, aidx = lane & 7;
    const int arow = ((amat & 1) << 3) + aidx;
    const int aksel = amat >> 1;
    const int a7 = arow & 7;
    const int bl_ = lane & 15, brin = bl_ & 7, bksel = bl_ >> 3;
    u32 bob[8];
#pragma unroll
    for (int nj = 0; nj < 8; nj++)
        bob[nj] = sb + R_W + (u32)((64 * w + 8 * nj + brin) * 256);

    // hoist B fragments for nj 0..3 (held for all 512 steps)
    u32 Br[8][4][2];
#pragma unroll
    for (int ks = 0; ks < 8; ks++) {
        const u32 swB = 16u * (u32)((2 * ks + bksel) ^ brin);
#pragma unroll
        for (int nj = 0; nj < 4; nj++)
            ldm2(Br[ks][nj][0], Br[ks][nj][1], bob[nj] + swB);
    }

    // epilogue decode: thread owns h(erow, col j = 16w + 2nj + hcsel), nj 0..7
    const int q = lane >> 2, t4 = lane & 3, rs = t4 & 1, hcsel = t4 >> 1;
    const int erow = q + 8 * rs;

    // direct A(t+1) addressing (STS.16 per nj)
    u32 aoffs[8];
#pragma unroll
    for (int nj = 0; nj < 8; nj++) {
        int j = 16 * w + 2 * nj + hcsel;
        aoffs[nj] = (u32)(erow * 256 + (((j >> 3) ^ (erow & 7)) << 4) + ((j & 7) * 2));
    }
    // stage write base (fp32, [16][132] per parity buffer)
    const u32 stw = (u32)((erow * 132 + 16 * w + hcsel) * 4);

    // out read/STG mapping (coalesced)
    const int orow = tid >> 4;
    const int oc8 = (tid & 15) * 8;
    float* outp = out + (b0 + orow) * (long)THX + oc8;
    const u32 str = (u32)((orow * 132 + oc8) * 4);

    const uint2* xzp = g_xzh + (long)cta * T_DIM * 2048;
    uint2 xz[8];
#pragma unroll
    for (int nj = 0; nj < 8; nj++)
        xz[nj] = xzp[nj * 256 + tid];

    float cst[8];
#pragma unroll
    for (int nj = 0; nj < 8; nj++) cst[nj] = 0.0f;

    for (int t = 0; t < T_DIM; t++) {
        __syncthreads();   // orders epilogue(t-1) writes before phase-t reads

        // coalesced out-write for step t-1 (overlaps with MMA below)
        if (t > 0) {
            const u32 sbuf = R_ST + (u32)(((t - 1) & 1) * STG_B);
            float4 h0 = *(const float4*)(smc + sbuf + str);
            float4 h1 = *(const float4*)(smc + sbuf + str + 16);
            *(float4*)(outp + (long)(t - 1) * H_DIM)     = h0;
            *(float4*)(outp + (long)(t - 1) * H_DIM + 4) = h1;
        }

        const u32 aob = sb + R_A + (u32)((t & 1) * 4096) + (u32)(arow * 256);

        float acc[8][4];
#pragma unroll
        for (int nj = 0; nj < 8; nj++)
#pragma unroll
            for (int e = 0; e < 4; e++) acc[nj][e] = 0.0f;

#pragma unroll
        for (int ks = 0; ks < 8; ks++) {
            u32 A0[4];
            ldm4(A0, aob + 16u * (u32)((2 * ks + aksel) ^ a7));
            const u32 swB = 16u * (u32)((2 * ks + bksel) ^ brin);
            u32 B4[4][2];
#pragma unroll
            for (int nj = 4; nj < 8; nj++)
                ldm2(B4[nj - 4][0], B4[nj - 4][1], bob[nj] + swB);
#pragma unroll
            for (int nj = 0; nj < 4; nj++)
                mma_f16(acc[nj], A0, Br[ks][nj][0], Br[ks][nj][1]);
#pragma unroll
            for (int nj = 4; nj < 8; nj++)
                mma_f16(acc[nj], A0, B4[nj - 4][0], B4[nj - 4][1]);
        }

        // epilogue: gates + state; h -> stage[t&1] (STS.32) + A(t+1) (STS.16)
        const u32 stbuf = R_ST + (u32)((t & 1) * STG_B);
        const u32 anext = R_A + (u32)(((t + 1) & 1) * 4096);
        const bool notlast = (t + 1 < T_DIM);
#pragma unroll
        for (int nj = 0; nj < 8; nj++) {
            float2 xlo = __half22float2(*(__half2*)&xz[nj].x);
            float2 xhi = __half22float2(*(__half2*)&xz[nj].y);
            float v0 = acc[nj][0] + xlo.x;
            float v1 = acc[nj][1] + xlo.y;
            float v2 = acc[nj][2] + xhi.x;
            float v3 = acc[nj][3] + xhi.y;
            float p0 = __shfl_xor_sync(0xffffffffu, v0, 1);
            float p1 = __shfl_xor_sync(0xffffffffu, v1, 1);
            float p2 = __shfl_xor_sync(0xffffffffu, v2, 1);
            float p3 = __shfl_xor_sync(0xffffffffu, v3, 1);
            float zi = rs ? p2 : v0;
            float zf = rs ? p3 : v1;
            float zg = rs ? v2 : p0;
            float zo = rs ? v3 : p1;
            float ig = sig_ap(zi);
            float fg = sig_ap(zf);
            float gg = tanh_ap(zg);
            float og = sig_ap(zo);
            float cn = fmaf(fg, cst[nj], ig * gg);
            cst[nj] = cn;
            float h = og * tanh_ap(cn);
            *(float*)(smc + stbuf + stw + (u32)(8 * nj)) = h;
            if (notlast)
                *(__half*)(smc + anext + aoffs[nj]) = __float2half_rn(h);
        }

        // prefetch xz(t+1) (after LDSM/MMA phase)
        if (notlast) {
            const uint2* s = xzp + (long)(t + 1) * 2048 + tid;
#pragma unroll
            for (int nj = 0; nj < 8; nj++)
                xz[nj] = s[nj * 256];
        }
    }

    // final out-write for t = T-1
    __syncthreads();
    {
        const u32 sbuf = R_ST + (u32)(((T_DIM - 1) & 1) * STG_B);
        float4 h0 = *(const float4*)(smc + sbuf + str);
        float4 h1 = *(const float4*)(smc + sbuf + str + 16);
        *(float4*)(outp + (long)(T_DIM - 1) * H_DIM)     = h0;
        *(float4*)(outp + (long)(T_DIM - 1) * H_DIM + 4) = h1;
    }
}

extern "C" void kernel_launch(void* const* d_in, const int* in_sizes, int n_in,
                              void* d_out, int out_size) {
    const float* x  = (const float*)d_in[0];   // [B,T,F]
    const float* Wx = (const float*)d_in[1];   // [F,512]
    const float* Wh = (const float*)d_in[2];   // [H,512]
    const float* b  = (const float*)d_in[3];   // [512]
    float* out = (float*)d_out;                // [B,T,H]

    cudaFuncSetAttribute(lstm_prepass, cudaFuncAttributeMaxDynamicSharedMemorySize, SMEM_PRE);
    cudaFuncSetAttribute(lstm_rec, cudaFuncAttributeMaxDynamicSharedMemorySize, SMEM_REC);

    lstm_prepass<<<512, NTH, SMEM_PRE>>>(x, Wx, b);
    lstm_rec<<<128, NTH, SMEM_REC>>>(Wh, out);
}

// round 17
// speedup vs baseline: 1.7809x; 1.0906x over previous
#include <cuda_runtime.h>
#include <cuda_fp16.h>
#include <cuda_bf16.h>
#include <cstdint>

// LSTM B=2048,T=512,F=64,H=128.
// Prepass: xz = x@Wx + b as a batched GEMM (single-term fp16 mma), M=128
//   (16 rows x 8 timesteps), N=512, K=64; fp16 quads to g_xzh in rec layout.
// Rec (R17 = R13 + full B hoist): 256 thr / 8 warps, warp owns 64 gate cols.
//   ALL 64 B fragments (8 ks x 8 nj) register-resident for the whole time
//   loop -> per-step LDSM is A-only (8 x ldm4). Two syncs/step as in R13.

#define T_DIM 512
#define F_DIM 64
#define H_DIM 128
#define TFX   (T_DIM * F_DIM)
#define THX   (T_DIM * H_DIM)
#define NTH   256

// rec smem
#define R_W   0
#define R_A   131072            // 2 x 4096 (A fp16 [16][128], double buffer)
#define R_ST  139264            // stage fp32 [16][132]
#define SMEM_REC (139264 + 16*132*4)

// prepass smem
#define P_W   0                 // W fp16 [512][64] ldmatrix layout, 64KB
#define P_A   65536             // A fp16 [128][64], double buffer 2x16KB
#define SMEM_PRE 98304

typedef uint32_t u32;
typedef unsigned long long u64;

__device__ uint2 g_xzh[134217728];   // 128 x 512 x 8 x 256 uint2 (1.07 GB)

static __device__ __forceinline__ u32 smaddr(const void* p) {
    u32 a;
    asm("{ .reg .u64 t; cvta.to.shared.u64 t, %1; cvt.u32.u64 %0, t; }" : "=r"(a) : "l"(p));
    return a;
}
static __device__ __forceinline__ void ldm4(u32* r, u32 ad) {
    asm volatile("ldmatrix.sync.aligned.m8n8.x4.shared.b16 {%0,%1,%2,%3}, [%4];"
                 : "=r"(r[0]), "=r"(r[1]), "=r"(r[2]), "=r"(r[3]) : "r"(ad));
}
static __device__ __forceinline__ void ldm2(u32& a, u32& b, u32 ad) {
    asm volatile("ldmatrix.sync.aligned.m8n8.x2.shared.b16 {%0,%1}, [%2];"
                 : "=r"(a), "=r"(b) : "r"(ad));
}
static __device__ __forceinline__ void mma_f16(float* c, const u32* a, u32 b0, u32 b1) {
    asm volatile(
        "mma.sync.aligned.m16n8k16.row.col.f32.f16.f16.f32 "
        "{%0,%1,%2,%3}, {%4,%5,%6,%7}, {%8,%9}, {%0,%1,%2,%3};"
        : "+f"(c[0]), "+f"(c[1]), "+f"(c[2]), "+f"(c[3])
        : "r"(a[0]), "r"(a[1]), "r"(a[2]), "r"(a[3]), "r"(b0), "r"(b1));
}
static __device__ __forceinline__ float tanh_ap(float x) {
    float r; asm("tanh.approx.f32 %0, %1;" : "=f"(r) : "f"(x)); return r;
}
static __device__ __forceinline__ float sig_ap(float x) {
    return fmaf(0.5f, tanh_ap(0.5f * x), 0.5f);
}
static __device__ __forceinline__ u32 cath(float a, float b) {
    __half2 h2 = __floats2half2_rn(a, b);
    return *(u32*)&h2;
}

// ============================ prepass ======================================
__global__ __launch_bounds__(NTH)
void lstm_prepass(const float* __restrict__ x, const float* __restrict__ Wx,
                  const float* __restrict__ bias)
{
    extern __shared__ char smc[];
    const u32 sb = smaddr(smc);
    const int tid = threadIdx.x, w = tid >> 5, lane = tid & 31;
    const int cta = blockIdx.x >> 2;
    const int t0 = (blockIdx.x & 3) * 128;
    const long b0 = (long)cta * 16;

    // W fp16, ldmatrix layout [n=512][k=64], 128B rows
    for (int idx = tid; idx < 512 * 64; idx += NTH) {
        int n = idx >> 6, k = idx & 63;
        int col = 128 * (n & 3) + (n >> 2);
        __half hv = __float2half_rn(Wx[k * 512 + col]);
        u32 off = (u32)(n * 128 + (((k >> 3) ^ (n & 7)) << 4) + (k & 7) * 2);
        *(__half*)(smc + P_W + off) = hv;
    }
    __syncthreads();

    const int amat = lane >> 3, aidx = lane & 7;
    const int arow = ((amat & 1) << 3) + aidx;
    const int aksel = amat >> 1;
    const int a7 = arow & 7;
    const int bl_ = lane & 15, brin = bl_ & 7, bksel = bl_ >> 3;

    u32 Br[4][8][2];
#pragma unroll
    for (int ks = 0; ks < 4; ks++) {
        const u32 swB = 16u * (u32)((2 * ks + bksel) ^ brin);
#pragma unroll
        for (int nj = 0; nj < 8; nj++)
            ldm2(Br[ks][nj][0], Br[ks][nj][1],
                 sb + P_W + (u32)((64 * w + 8 * nj + brin) * 128) + swB);
    }

    const int t4 = lane & 3;
    float b2[8][2];
#pragma unroll
    for (int nj = 0; nj < 8; nj++)
#pragma unroll
        for (int e = 0; e < 2; e++) {
            int n = 64 * w + 8 * nj + 2 * t4 + e;
            b2[nj][e] = bias[128 * (n & 3) + (n >> 2)];
        }

    const int brow = tid >> 1, part = tid & 1;
    const int tt = brow >> 4, bb = brow & 15;
    const float* xbase = x + (b0 + bb) * (long)TFX + (t0 + tt) * F_DIM + 32 * part;
    u32 aoff[4];
#pragma unroll
    for (int j = 0; j < 4; j++)
        aoff[j] = (u32)(brow * 128 + (((4 * part + j) ^ (brow & 7)) << 4));

    auto build = [&](int it, int buf) {
        const float* s = xbase + it * 8 * F_DIM;
        float4 q[8];
#pragma unroll
        for (int j = 0; j < 8; j++) q[j] = *(const float4*)(s + 4 * j);
        const u32 base = (u32)(P_A + buf * 16384);
#pragma unroll
        for (int j = 0; j < 4; j++) {
            uint4 pk;
            pk.x = cath(q[2 * j].x, q[2 * j].y);
            pk.y = cath(q[2 * j].z, q[2 * j].w);
            pk.z = cath(q[2 * j + 1].x, q[2 * j + 1].y);
            pk.w = cath(q[2 * j + 1].z, q[2 * j + 1].w);
            *(uint4*)(smc + base + aoff[j]) = pk;
        }
    };

    build(0, 0);
    __syncthreads();

    for (int it = 0; it < 16; it++) {
        if (it + 1 < 16) build(it + 1, (it + 1) & 1);

        const u32 ab = sb + P_A + (u32)((it & 1) * 16384);
#pragma unroll
        for (int mi = 0; mi < 8; mi++) {
            float acc[8][4];
#pragma unroll
            for (int nj = 0; nj < 8; nj++)
#pragma unroll
                for (int e = 0; e < 4; e++) acc[nj][e] = 0.0f;

#pragma unroll
            for (int ks = 0; ks < 4; ks++) {
                u32 A0[4];
                ldm4(A0, ab + (u32)((16 * mi + arow) * 128)
                         + 16u * (u32)((2 * ks + aksel) ^ a7));
#pragma unroll
                for (int nj = 0; nj < 8; nj++)
                    mma_f16(acc[nj], A0, Br[ks][nj][0], Br[ks][nj][1]);
            }

            const int t = t0 + 8 * it + mi;
            uint2* dst = g_xzh + ((long)cta * T_DIM + t) * 2048 + tid;
#pragma unroll
            for (int nj = 0; nj < 8; nj++) {
                uint2 pk;
                pk.x = cath(acc[nj][0] + b2[nj][0], acc[nj][1] + b2[nj][1]);
                pk.y = cath(acc[nj][2] + b2[nj][0], acc[nj][3] + b2[nj][1]);
                dst[nj * 256] = pk;
            }
        }
        __syncthreads();
    }
}

// ============================ recurrent ====================================
// 256 threads / 8 warps; warp w owns gate cols [64w, 64w+64) = 8 n-tiles.
// All B fragments register-resident; per-step LDSM is A-only.
__global__ __launch_bounds__(NTH)
void lstm_rec(const float* __restrict__ Wh, float* __restrict__ out)
{
    extern __shared__ char smc[];
    const u32 sb = smaddr(smc);
    const int tid = threadIdx.x, w = tid >> 5, lane = tid & 31;
    const int cta = blockIdx.x;
    const long b0 = (long)cta * 16;

    // Wh fp16 [n=512][k=128], ldmatrix layout, 256B rows
    for (int idx = tid; idx < 512 * 128; idx += NTH) {
        int n = idx >> 7, k = idx & 127;
        int col = 128 * (n & 3) + (n >> 2);
        __half hv = __float2half_rn(Wh[k * 512 + col]);
        u32 off = (u32)(n * 256 + (((k >> 3) ^ (n & 7)) << 4) + (k & 7) * 2);
        *(__half*)(smc + R_W + off) = hv;
    }
    for (int i = tid; i < 8192 / 8; i += NTH)
        ((u64*)(smc + R_A))[i] = 0ull;
    __syncthreads();

    // fragment decode
    const int amat = lane >> 3, aidx = lane & 7;
    const int arow = ((amat & 1) << 3) + aidx;
    const int aksel = amat >> 1;
    const int a7 = arow & 7;
    const int bl_ = lane & 15, brin = bl_ & 7, bksel = bl_ >> 3;

    // hoist ALL B fragments (8 ks x 8 nj) — held for all 512 steps
    u32 Br[8][8][2];
#pragma unroll
    for (int ks = 0; ks < 8; ks++) {
        const u32 swB = 16u * (u32)((2 * ks + bksel) ^ brin);
#pragma unroll
        for (int nj = 0; nj < 8; nj++)
            ldm2(Br[ks][nj][0], Br[ks][nj][1],
                 sb + R_W + (u32)((64 * w + 8 * nj + brin) * 256) + swB);
    }

    // epilogue decode
    const int q = lane >> 2, t4 = lane & 3, rs = t4 & 1, hcsel = t4 >> 1;
    const int erow = q + 8 * rs;

    const uint2* xzp = g_xzh + (long)cta * T_DIM * 2048;
    uint2 xz[8];
#pragma unroll
    for (int nj = 0; nj < 8; nj++)
        xz[nj] = xzp[nj * 256 + tid];

    float cst[8];
#pragma unroll
    for (int nj = 0; nj < 8; nj++) cst[nj] = 0.0f;

    // out/A-build pass mapping
    const int orow = tid >> 4;
    const int oc8 = (tid & 15) * 8;
    float* outp = out + (b0 + orow) * (long)THX + oc8;
    const u32 abOff = (u32)(orow * 256 + (((oc8 >> 3) ^ (orow & 7)) << 4));

    for (int t = 0; t < T_DIM; t++) {
        __syncthreads();   // A(t) buffer complete; stage free

        const u32 aob = sb + R_A + (u32)((t & 1) * 4096) + (u32)(arow * 256);

        float acc[8][4];
#pragma unroll
        for (int nj = 0; nj < 8; nj++)
#pragma unroll
            for (int e = 0; e < 4; e++) acc[nj][e] = 0.0f;

#pragma unroll
        for (int ks = 0; ks < 8; ks++) {
            u32 A0[4];
            ldm4(A0, aob + 16u * (u32)((2 * ks + aksel) ^ a7));
#pragma unroll
            for (int nj = 0; nj < 8; nj++)
                mma_f16(acc[nj], A0, Br[ks][nj][0], Br[ks][nj][1]);
        }

        // epilogue: z = acc + xz, shfl gate exchange, approx gates, stage h
#pragma unroll
        for (int nj = 0; nj < 8; nj++) {
            float2 xlo = __half22float2(*(__half2*)&xz[nj].x);
            float2 xhi = __half22float2(*(__half2*)&xz[nj].y);
            float v0 = acc[nj][0] + xlo.x;
            float v1 = acc[nj][1] + xlo.y;
            float v2 = acc[nj][2] + xhi.x;
            float v3 = acc[nj][3] + xhi.y;
            float p0 = __shfl_xor_sync(0xffffffffu, v0, 1);
            float p1 = __shfl_xor_sync(0xffffffffu, v1, 1);
            float p2 = __shfl_xor_sync(0xffffffffu, v2, 1);
            float p3 = __shfl_xor_sync(0xffffffffu, v3, 1);
            float zi = rs ? p2 : v0;
            float zf = rs ? p3 : v1;
            float zg = rs ? v2 : p0;
            float zo = rs ? v3 : p1;
            float ig = sig_ap(zi);
            float fg = sig_ap(zf);
            float gg = tanh_ap(zg);
            float og = sig_ap(zo);
            float cn = fmaf(fg, cst[nj], ig * gg);
            cst[nj] = cn;
            float h = og * tanh_ap(cn);
            *(float*)(smc + R_ST + (u32)((erow * 132 + 16 * w + 2 * nj + hcsel) * 4)) = h;
        }

        // prefetch xz(t+1) (after LDSM phase -> never queues ahead of it)
        if (t + 1 < T_DIM) {
            const uint2* s = xzp + (long)(t + 1) * 2048 + tid;
#pragma unroll
            for (int nj = 0; nj < 8; nj++)
                xz[nj] = s[nj * 256];
        }

        __syncthreads();   // stage complete

        // coalesced out write + A(t+1) build from stage
        float hv[8];
        *(float4*)(hv)     = *(const float4*)(smc + R_ST + (u32)((orow * 132 + oc8) * 4));
        *(float4*)(hv + 4) = *(const float4*)(smc + R_ST + (u32)((orow * 132 + oc8 + 4) * 4));
        *(float4*)(outp + (long)t * H_DIM)     = *(const float4*)(hv);
        *(float4*)(outp + (long)t * H_DIM + 4) = *(const float4*)(hv + 4);
        if (t + 1 < T_DIM) {
            uint4 pk;
            pk.x = cath(hv[0], hv[1]);
            pk.y = cath(hv[2], hv[3]);
            pk.z = cath(hv[4], hv[5]);
            pk.w = cath(hv[6], hv[7]);
            *(uint4*)(smc + R_A + (u32)(((t + 1) & 1) * 4096) + abOff) = pk;
        }
    }
}

extern "C" void kernel_launch(void* const* d_in, const int* in_sizes, int n_in,
                              void* d_out, int out_size) {
    const float* x  = (const float*)d_in[0];   // [B,T,F]
    const float* Wx = (const float*)d_in[1];   // [F,512]
    const float* Wh = (const float*)d_in[2];   // [H,512]
    const float* b  = (const float*)d_in[3];   // [512]
    float* out = (float*)d_out;                // [B,T,H]

    cudaFuncSetAttribute(lstm_prepass, cudaFuncAttributeMaxDynamicSharedMemorySize, SMEM_PRE);
    cudaFuncSetAttribute(lstm_rec, cudaFuncAttributeMaxDynamicSharedMemorySize, SMEM_REC);

    lstm_prepass<<<512, NTH, SMEM_PRE>>>(x, Wx, b);
    lstm_rec<<<128, NTH, SMEM_REC>>>(Wh, out);
}